// round 6
// baseline (speedup 1.0000x reference)
#include <cuda_runtime.h>
#include <cuda_fp16.h>
#include <math.h>

#define NN 100000
#define CC 16
#define EE 3200000
#define FF 512
#define HH 64
#define VN (2*NN)

#define NBLK2 196        // ceil(VN/1024)
#define EB4   6250       // 2*EE/(256*4)
#define PB2   25000      // VN warps / 8 warps-per-block
#define FB    6250       // NN*CC/256
#define GEMM_BLKS 782    // ceil(NN/128)
#define MASKW 3125       // NN/32

// ---------------- scratch (device globals: allocation-free) ----------------
__device__ int      g_cnt[VN];
__device__ int      g_tmpscan[VN];
__device__ int      g_rowptr[VN + 1];
__device__ int      g_wp[VN];
__device__ int      g_blksum[256];
__device__ unsigned g_trainbit[MASKW];
__device__ uint2    g_edge8[2 * EE];       // {src, half2(exp(e_l0), exp(e_l1))}
__device__ uint4    g_li16[NN * 2];        // label_init fp16 (2 uint4 = 16 halves/row)
__device__ uint4    g_oh16[NN * 2];        // one_hot fp16
__device__ uint4    g_h016[VN * 2];        // layer-0 output fp16, both graphs
__device__ float    g_hg[VN * CC];         // layer-1 output fp32, both graphs
__device__ float    g_mlp[NN * CC];        // fused MLP output (after w2,b2)

// ---------------- tf32 mma helpers ----------------
__device__ __forceinline__ unsigned f2tf32(float x) {
    unsigned r;
    asm("cvt.rna.tf32.f32 %0, %1;" : "=r"(r) : "f"(x));
    return r;
}
__device__ __forceinline__ void mma_tf32(float c[4], const unsigned a[4], const unsigned b[2]) {
    asm volatile("mma.sync.aligned.m16n8k8.row.col.f32.tf32.tf32.f32 "
                 "{%0,%1,%2,%3}, {%4,%5,%6,%7}, {%8,%9}, {%0,%1,%2,%3};"
                 : "+f"(c[0]), "+f"(c[1]), "+f"(c[2]), "+f"(c[3])
                 : "r"(a[0]), "r"(a[1]), "r"(a[2]), "r"(a[3]), "r"(b[0]), "r"(b[1]));
}
__device__ __forceinline__ bool is_train(int d) {
    return (g_trainbit[d >> 5] >> (d & 31)) & 1u;
}

// ---------------- prep: bitmask + fp16 conversions --------------------------
__global__ __launch_bounds__(256) void prep_kernel(const int* __restrict__ train,
                                                   const float* __restrict__ label_init,
                                                   const float* __restrict__ one_hot) {
    int i = blockIdx.x * blockDim.x + threadIdx.x;     // grid covers NN*CC/2 = 800000
    if (i < NN * CC / 2) {
        float2 li = ((const float2*)label_init)[i];
        float2 oh = ((const float2*)one_hot)[i];
        __half2 l2 = __floats2half2_rn(li.x, li.y);
        __half2 o2 = __floats2half2_rn(oh.x, oh.y);
        ((unsigned*)g_li16)[i] = *(unsigned*)&l2;
        ((unsigned*)g_oh16)[i] = *(unsigned*)&o2;
    }
    if (i < MASKW) {
        unsigned m = 0;
        #pragma unroll 8
        for (int b = 0; b < 32; b++)
            m |= (train[i * 32 + b] != 0 ? 1u : 0u) << b;
        g_trainbit[i] = m;
    }
}

// ---------------- hist (bitmask + int4 vectorized) --------------------------
__global__ __launch_bounds__(256) void hist_kernel(const int* __restrict__ dst) {
    int t = blockIdx.x * 256 + threadIdx.x;            // covers 4 edges
    int4 d4 = ((const int4*)dst)[t];
    int base = ((t << 2) >= EE) ? NN : 0;              // EE % 4 == 0
    if (!is_train(d4.x)) atomicAdd(&g_cnt[base + d4.x], 1);
    if (!is_train(d4.y)) atomicAdd(&g_cnt[base + d4.y], 1);
    if (!is_train(d4.z)) atomicAdd(&g_cnt[base + d4.z], 1);
    if (!is_train(d4.w)) atomicAdd(&g_cnt[base + d4.w], 1);
}

// ---------------- scan stage 1 ----------------
__global__ __launch_bounds__(1024) void scan1_kernel() {
    __shared__ int s[1024];
    int i = blockIdx.x * 1024 + threadIdx.x;
    int v = (i < VN) ? g_cnt[i] : 0;
    s[threadIdx.x] = v;
    __syncthreads();
    #pragma unroll
    for (int off = 1; off < 1024; off <<= 1) {
        int t = (threadIdx.x >= off) ? s[threadIdx.x - off] : 0;
        __syncthreads();
        s[threadIdx.x] += t;
        __syncthreads();
    }
    if (i < VN) g_tmpscan[i] = s[threadIdx.x];
    if (threadIdx.x == 1023) g_blksum[blockIdx.x] = s[1023];
}

// ---------------- scan stage 2 (block-offset scan inlined per block) --------
__global__ __launch_bounds__(1024) void scan3_kernel() {
    __shared__ int s2[256];
    int t = threadIdx.x;
    int v2 = 0;
    if (t < 256) {
        v2 = (t < NBLK2) ? g_blksum[t] : 0;
        s2[t] = v2;
    }
    __syncthreads();
    #pragma unroll
    for (int off = 1; off < 256; off <<= 1) {
        int u = 0;
        if (t < 256 && t >= off) u = s2[t - off];
        __syncthreads();
        if (t < 256) s2[t] += u;
        __syncthreads();
    }
    if (t < 256) s2[t] -= v2;                          // exclusive
    __syncthreads();

    int i = blockIdx.x * 1024 + t;
    if (i < VN) {
        int incl = g_tmpscan[i] + s2[blockIdx.x];
        g_rowptr[i + 1] = incl;
        g_wp[i] = incl - g_cnt[i];
    }
    if (i == 0) g_rowptr[0] = 0;
}

// ---------------- fused: tf32 GEMM+MLP2 (blocks < GEMM_BLKS) + CSR scatter --
__global__ __launch_bounds__(256) void scatter_gemm_kernel(
        const int* __restrict__ src, const int* __restrict__ dst,
        const float* __restrict__ e_edge,
        const float* __restrict__ X, const float* __restrict__ w1,
        const float* __restrict__ b1v,
        const float* __restrict__ w2, const float* __restrict__ b2) {
    __shared__ __align__(16) float Xs[16][136];   // mainloop: [k][row]
    __shared__ __align__(16) float Ws[16][72];    // mainloop: [k][n]; epilogue: w2

    if (blockIdx.x < GEMM_BLKS) {
        int tid = threadIdx.x;
        int lane = tid & 31;
        int gid = lane >> 2, tig = lane & 3;
        int m0 = (tid >> 5) * 16;
        int n0 = blockIdx.x * 128;

        float acc[8][4];
        #pragma unroll
        for (int nt = 0; nt < 8; nt++)
            #pragma unroll
            for (int r = 0; r < 4; r++) acc[nt][r] = 0.f;

        for (int k0 = 0; k0 < FF; k0 += 16) {
            #pragma unroll
            for (int r = 0; r < 2; r++) {
                int v = tid + r * 256;
                int row = v >> 2, kq = v & 3;
                int gn = n0 + row;
                float4 xv = make_float4(0.f, 0.f, 0.f, 0.f);
                if (gn < NN) xv = *(const float4*)(X + (size_t)gn * FF + k0 + kq * 4);
                Xs[kq * 4 + 0][row] = xv.x;
                Xs[kq * 4 + 1][row] = xv.y;
                Xs[kq * 4 + 2][row] = xv.z;
                Xs[kq * 4 + 3][row] = xv.w;
            }
            {
                int kk = tid >> 4, nq = tid & 15;
                float4 wv = *(const float4*)(w1 + (size_t)(k0 + kk) * HH + nq * 4);
                Ws[kk][nq * 4 + 0] = __uint_as_float(f2tf32(wv.x));
                Ws[kk][nq * 4 + 1] = __uint_as_float(f2tf32(wv.y));
                Ws[kk][nq * 4 + 2] = __uint_as_float(f2tf32(wv.z));
                Ws[kk][nq * 4 + 3] = __uint_as_float(f2tf32(wv.w));
            }
            __syncthreads();
            #pragma unroll
            for (int ks = 0; ks < 2; ks++) {
                unsigned a[4];
                a[0] = f2tf32(Xs[ks * 8 + tig    ][m0 + gid    ]);
                a[1] = f2tf32(Xs[ks * 8 + tig    ][m0 + gid + 8]);
                a[2] = f2tf32(Xs[ks * 8 + tig + 4][m0 + gid    ]);
                a[3] = f2tf32(Xs[ks * 8 + tig + 4][m0 + gid + 8]);
                #pragma unroll
                for (int nt = 0; nt < 8; nt++) {
                    unsigned b[2];
                    b[0] = __float_as_uint(Ws[ks * 8 + tig    ][nt * 8 + gid]);
                    b[1] = __float_as_uint(Ws[ks * 8 + tig + 4][nt * 8 + gid]);
                    mma_tf32(acc[nt], a, b);
                }
            }
            __syncthreads();
        }

        // epilogue: stage w2 into retired Ws smem, then register-level MLP2
        float* sw2 = &Ws[0][0];                   // 1024 floats <= 1152 avail
        for (int i = tid; i < HH * CC; i += 256) sw2[i] = w2[i];
        __syncthreads();

        #pragma unroll
        for (int rr = 0; rr < 2; rr++) {
            float4 p[4];
            #pragma unroll
            for (int q = 0; q < 4; q++) p[q] = make_float4(0.f, 0.f, 0.f, 0.f);
            #pragma unroll
            for (int nt = 0; nt < 8; nt++) {
                #pragma unroll
                for (int j = 0; j < 2; j++) {
                    int k = nt * 8 + 2 * tig + j;
                    float hv = fmaxf(acc[nt][rr * 2 + j] + b1v[k], 0.f);
                    const float4* wr = (const float4*)(sw2 + k * CC);
                    #pragma unroll
                    for (int q = 0; q < 4; q++) {
                        float4 wv = wr[q];
                        p[q].x = fmaf(hv, wv.x, p[q].x);
                        p[q].y = fmaf(hv, wv.y, p[q].y);
                        p[q].z = fmaf(hv, wv.z, p[q].z);
                        p[q].w = fmaf(hv, wv.w, p[q].w);
                    }
                }
            }
            #pragma unroll
            for (int q = 0; q < 4; q++) {
                #pragma unroll
                for (int off = 1; off <= 2; off <<= 1) {
                    p[q].x += __shfl_xor_sync(0xFFFFFFFFu, p[q].x, off);
                    p[q].y += __shfl_xor_sync(0xFFFFFFFFu, p[q].y, off);
                    p[q].z += __shfl_xor_sync(0xFFFFFFFFu, p[q].z, off);
                    p[q].w += __shfl_xor_sync(0xFFFFFFFFu, p[q].w, off);
                }
            }
            int grow = n0 + m0 + rr * 8 + gid;
            if (grow < NN) {
                float4 qv = (tig == 0) ? p[0] : (tig == 1) ? p[1] : (tig == 2) ? p[2] : p[3];
                float4 bq = ((const float4*)b2)[tig];
                qv.x += bq.x; qv.y += bq.y; qv.z += bq.z; qv.w += bq.w;
                ((float4*)(g_mlp + (size_t)grow * CC))[tig] = qv;
            }
        }
        return;
    }

    // ---- CSR scatter branch (bitmask + x4 vectorized, 8B records) ----
    int t = (blockIdx.x - GEMM_BLKS) * 256 + threadIdx.x;   // covers 4 edges
    int4   s4 = ((const int4*)src)[t];
    int4   d4 = ((const int4*)dst)[t];
    float4 e0 = ((const float4*)e_edge)[t];
    float4 e1 = ((const float4*)(e_edge + 2 * (size_t)EE))[t];
    int base = ((t << 2) >= EE) ? NN : 0;
    // softmax max-shift cancels; exp(|e|<6) safe; fp16 range ok (exp<=e^6~403)
    if (!is_train(d4.x)) {
        int p = atomicAdd(&g_wp[base + d4.x], 1);
        __half2 w = __floats2half2_rn(__expf(e0.x), __expf(e1.x));
        g_edge8[p] = make_uint2((unsigned)s4.x, *(unsigned*)&w);
    }
    if (!is_train(d4.y)) {
        int p = atomicAdd(&g_wp[base + d4.y], 1);
        __half2 w = __floats2half2_rn(__expf(e0.y), __expf(e1.y));
        g_edge8[p] = make_uint2((unsigned)s4.y, *(unsigned*)&w);
    }
    if (!is_train(d4.z)) {
        int p = atomicAdd(&g_wp[base + d4.z], 1);
        __half2 w = __floats2half2_rn(__expf(e0.z), __expf(e1.z));
        g_edge8[p] = make_uint2((unsigned)s4.z, *(unsigned*)&w);
    }
    if (!is_train(d4.w)) {
        int p = atomicAdd(&g_wp[base + d4.w], 1);
        __half2 w = __floats2half2_rn(__expf(e0.w), __expf(e1.w));
        g_edge8[p] = make_uint2((unsigned)s4.w, *(unsigned*)&w);
    }
}

// ---------------- propagate (gather, warp-per-vnode, 2 lanes/edge, fp16 h) --
template <int LAYER>
__global__ __launch_bounds__(256) void prop_kernel(const float* __restrict__ one_hot) {
    int v    = (blockIdx.x * blockDim.x + threadIdx.x) >> 5;
    int lane = threadIdx.x & 31;
    if (v >= VN) return;
    int n = (v < NN) ? v : v - NN;

    if (is_train(n)) {
        if (LAYER == 0) {
            if (lane < 2) g_h016[(size_t)v * 2 + lane] = g_oh16[(size_t)n * 2 + lane];
        } else {
            if (lane < CC) g_hg[(size_t)v * CC + lane] = one_hot[(size_t)n * CC + lane];
        }
        return;
    }

    const uint4* hbase = (LAYER == 0) ? g_li16
                                      : (g_h016 + ((v < NN) ? 0 : (size_t)NN * 2));
    int beg = g_rowptr[v], end = g_rowptr[v + 1];
    int half = lane & 1;                 // which 8-class half this lane owns

    float a[8];
    #pragma unroll
    for (int q = 0; q < 8; q++) a[q] = 0.f;
    float sw = 0.f;

    for (int j = beg + (lane >> 1); j < end; j += 16) {
        uint2 rec = g_edge8[j];
        int s = (int)rec.x;
        __half2 wh = *(__half2*)&rec.y;
        float w = (LAYER == 0) ? __low2float(wh) : __high2float(wh);
        uint4 u = hbase[(size_t)s * 2 + half];
        float2 f0 = __half22float2(*(__half2*)&u.x);
        float2 f1 = __half22float2(*(__half2*)&u.y);
        float2 f2 = __half22float2(*(__half2*)&u.z);
        float2 f3 = __half22float2(*(__half2*)&u.w);
        a[0] = fmaf(w, f0.x, a[0]); a[1] = fmaf(w, f0.y, a[1]);
        a[2] = fmaf(w, f1.x, a[2]); a[3] = fmaf(w, f1.y, a[3]);
        a[4] = fmaf(w, f2.x, a[4]); a[5] = fmaf(w, f2.y, a[5]);
        a[6] = fmaf(w, f3.x, a[6]); a[7] = fmaf(w, f3.y, a[7]);
        sw += w;
    }
    #pragma unroll
    for (int off = 2; off < 32; off <<= 1) {
        #pragma unroll
        for (int q = 0; q < 8; q++)
            a[q] += __shfl_xor_sync(0xFFFFFFFFu, a[q], off);
        sw += __shfl_xor_sync(0xFFFFFFFFu, sw, off);
    }
    if (lane < 2) {
        float inv = (sw > 0.f) ? (1.f / sw) : 0.f;
        #pragma unroll
        for (int q = 0; q < 8; q++) a[q] *= inv;
        if (LAYER == 0) {
            __half2 o0 = __floats2half2_rn(a[0], a[1]);
            __half2 o1 = __floats2half2_rn(a[2], a[3]);
            __half2 o2 = __floats2half2_rn(a[4], a[5]);
            __half2 o3 = __floats2half2_rn(a[6], a[7]);
            uint4 u;
            u.x = *(unsigned*)&o0; u.y = *(unsigned*)&o1;
            u.z = *(unsigned*)&o2; u.w = *(unsigned*)&o3;
            g_h016[(size_t)v * 2 + half] = u;
        } else {
            float* op = g_hg + (size_t)v * CC + half * 8;
            ((float4*)op)[0] = make_float4(a[0], a[1], a[2], a[3]);
            ((float4*)op)[1] = make_float4(a[4], a[5], a[6], a[7]);
        }
    }
}

// ---------------- final: attention combine + residual mix -------------------
__global__ __launch_bounds__(256) void final_kernel(const float* __restrict__ att,
                                                    const float* __restrict__ alpha,
                                                    float* __restrict__ out) {
    int idx = blockIdx.x * blockDim.x + threadIdx.x;
    if (idx >= NN * CC) return;
    int n = idx >> 4, c = idx & 15;

    float a0 = att[n * 2 + 0], a1 = att[n * 2 + 1];
    float mx = fmaxf(a0, a1);
    float e0 = expf(a0 - mx), e1 = expf(a1 - mx);
    float inv = 1.f / (e0 + e1);

    float sa = 1.f / (1.f + expf(-alpha[n]));
    float logits = g_hg[idx] * (e0 * inv) + g_hg[(size_t)(NN + n) * CC + c] * (e1 * inv);
    out[idx] = sa * logits + (1.f - sa) * g_mlp[idx];
}

// ---------------- launcher ----------------
extern "C" void kernel_launch(void* const* d_in, const int* in_sizes, int n_in,
                              void* d_out, int out_size) {
    (void)in_sizes; (void)n_in; (void)out_size;
    const float* features   = (const float*)d_in[0];
    const float* label_init = (const float*)d_in[1];
    const float* one_hot    = (const float*)d_in[2];
    const float* alpha      = (const float*)d_in[3];
    const float* attention  = (const float*)d_in[4];
    const float* e_edge     = (const float*)d_in[5];
    const float* w1         = (const float*)d_in[6];
    const float* b1         = (const float*)d_in[7];
    const float* w2         = (const float*)d_in[8];
    const float* b2         = (const float*)d_in[9];
    const int*   src        = (const int*)d_in[10];
    const int*   dst        = (const int*)d_in[11];
    const int*   train      = (const int*)d_in[12];
    float*       out        = (float*)d_out;

    void* cnt_ptr = nullptr;
    cudaGetSymbolAddress(&cnt_ptr, g_cnt);
    cudaMemsetAsync(cnt_ptr, 0, VN * sizeof(int));

    prep_kernel<<<(NN * CC / 2 + 255) / 256, 256>>>(train, label_init, one_hot); // 1
    hist_kernel<<<EB4, 256>>>(dst);                                              // 2
    scan1_kernel<<<NBLK2, 1024>>>();                                             // 3
    scan3_kernel<<<NBLK2, 1024>>>();                                             // 4 (ncu)
    scatter_gemm_kernel<<<GEMM_BLKS + EB4, 256>>>(src, dst, e_edge,
                                                  features, w1, b1, w2, b2);     // 5
    prop_kernel<0><<<PB2, 256>>>(one_hot);                                       // 6
    prop_kernel<1><<<PB2, 256>>>(one_hot);                                       // 7
    final_kernel<<<FB, 256>>>(attention, alpha, out);                            // 8
}

// round 7
// speedup vs baseline: 1.5624x; 1.5624x over previous
#include <cuda_runtime.h>
#include <cuda_fp16.h>
#include <math.h>

#define NN 100000
#define CC 16
#define EE 3200000
#define FF 512
#define HH 64
#define VN (2*NN)

#define NBLK2 196        // ceil(VN/1024)
#define EB4   6250       // 2*EE/(256*4)
#define PB2   25000      // VN warps / 8 warps-per-block
#define FB    6250       // NN*CC/256
#define GEMM_BLKS 782    // ceil(NN/128)
#define MASKW 3125       // NN/32

// ---------------- scratch (device globals: allocation-free) ----------------
__device__ int      g_cnt[VN];
__device__ int      g_tmpscan[VN];
__device__ int      g_rowptr[VN + 1];
__device__ int      g_wp[VN];
__device__ int      g_blksum[256];
__device__ unsigned g_trainbit[MASKW];
__device__ uint2    g_edge8[2 * EE];       // {src, half2(exp(e_l0), exp(e_l1))}
__device__ uint4    g_li16[NN * 2];        // label_init fp16 (2 uint4 = 16 halves/row)
__device__ uint4    g_oh16[NN * 2];        // one_hot fp16
__device__ uint4    g_h016[VN * 2];        // layer-0 output fp16, both graphs
__device__ float    g_hg[VN * CC];         // layer-1 output fp32, both graphs
__device__ float    g_hidden[NN * HH];     // MLP hidden (relu(X@W1+b1))
__device__ float    g_w1t[FF * HH];        // tf32-rounded W1

// ---------------- tf32 mma helpers ----------------
__device__ __forceinline__ unsigned f2tf32(float x) {
    unsigned r;
    asm("cvt.rna.tf32.f32 %0, %1;" : "=r"(r) : "f"(x));
    return r;
}
__device__ __forceinline__ void mma_tf32(float c[4], const unsigned a[4], const unsigned b[2]) {
    asm volatile("mma.sync.aligned.m16n8k8.row.col.f32.tf32.tf32.f32 "
                 "{%0,%1,%2,%3}, {%4,%5,%6,%7}, {%8,%9}, {%0,%1,%2,%3};"
                 : "+f"(c[0]), "+f"(c[1]), "+f"(c[2]), "+f"(c[3])
                 : "r"(a[0]), "r"(a[1]), "r"(a[2]), "r"(a[3]), "r"(b[0]), "r"(b[1]));
}
__device__ __forceinline__ bool is_train(int d) {
    return (g_trainbit[d >> 5] >> (d & 31)) & 1u;
}

// ---------------- prep: bitmask + W1 tf32 + fp16 conversions ----------------
__global__ __launch_bounds__(256) void prep_kernel(const int* __restrict__ train,
                                                   const float* __restrict__ w1,
                                                   const float* __restrict__ label_init,
                                                   const float* __restrict__ one_hot) {
    int i = blockIdx.x * blockDim.x + threadIdx.x;     // grid covers NN*CC/2 = 800000
    if (i < NN * CC / 2) {
        float2 li = ((const float2*)label_init)[i];
        float2 oh = ((const float2*)one_hot)[i];
        __half2 l2 = __floats2half2_rn(li.x, li.y);
        __half2 o2 = __floats2half2_rn(oh.x, oh.y);
        ((unsigned*)g_li16)[i] = *(unsigned*)&l2;
        ((unsigned*)g_oh16)[i] = *(unsigned*)&o2;
    }
    if (i < FF * HH) g_w1t[i] = __uint_as_float(f2tf32(w1[i]));
    if (i < MASKW) {
        unsigned m = 0;
        #pragma unroll 8
        for (int b = 0; b < 32; b++)
            m |= (train[i * 32 + b] != 0 ? 1u : 0u) << b;
        g_trainbit[i] = m;
    }
}

// ---------------- hist (bitmask + int4 vectorized) --------------------------
__global__ __launch_bounds__(256) void hist_kernel(const int* __restrict__ dst) {
    int t = blockIdx.x * 256 + threadIdx.x;            // covers 4 edges
    int4 d4 = ((const int4*)dst)[t];
    int base = ((t << 2) >= EE) ? NN : 0;              // EE % 4 == 0
    if (!is_train(d4.x)) atomicAdd(&g_cnt[base + d4.x], 1);
    if (!is_train(d4.y)) atomicAdd(&g_cnt[base + d4.y], 1);
    if (!is_train(d4.z)) atomicAdd(&g_cnt[base + d4.z], 1);
    if (!is_train(d4.w)) atomicAdd(&g_cnt[base + d4.w], 1);
}

// ---------------- scan stage 1 ----------------
__global__ __launch_bounds__(1024) void scan1_kernel() {
    __shared__ int s[1024];
    int i = blockIdx.x * 1024 + threadIdx.x;
    int v = (i < VN) ? g_cnt[i] : 0;
    s[threadIdx.x] = v;
    __syncthreads();
    #pragma unroll
    for (int off = 1; off < 1024; off <<= 1) {
        int t = (threadIdx.x >= off) ? s[threadIdx.x - off] : 0;
        __syncthreads();
        s[threadIdx.x] += t;
        __syncthreads();
    }
    if (i < VN) g_tmpscan[i] = s[threadIdx.x];
    if (threadIdx.x == 1023) g_blksum[blockIdx.x] = s[1023];
}

// ---------------- scan stage 2 (block-offset scan inlined per block) --------
__global__ __launch_bounds__(1024) void scan23_kernel() {
    __shared__ int s2[256];
    int t = threadIdx.x;
    int v2 = 0;
    if (t < 256) {
        v2 = (t < NBLK2) ? g_blksum[t] : 0;
        s2[t] = v2;
    }
    __syncthreads();
    #pragma unroll
    for (int off = 1; off < 256; off <<= 1) {
        int u = 0;
        if (t < 256 && t >= off) u = s2[t - off];
        __syncthreads();
        if (t < 256) s2[t] += u;
        __syncthreads();
    }
    if (t < 256) s2[t] -= v2;                          // exclusive
    __syncthreads();

    int i = blockIdx.x * 1024 + t;
    if (i < VN) {
        int incl = g_tmpscan[i] + s2[blockIdx.x];
        g_rowptr[i + 1] = incl;
        g_wp[i] = incl - g_cnt[i];
    }
    if (i == 0) g_rowptr[0] = 0;
}

// ---------------- fused: tf32 GEMM (blocks < GEMM_BLKS) + CSR scatter -------
// GEMM: relu(X[N,512]@W1t+b1) -> g_hidden. Simple epilogue, low regs (round-2 proven).
__global__ __launch_bounds__(256) void scatter_gemm_kernel(
        const int* __restrict__ src, const int* __restrict__ dst,
        const float* __restrict__ e_edge,
        const float* __restrict__ X, const float* __restrict__ bias) {
    __shared__ __align__(16) float Xs[16][136];   // [k][row], pad: conflict-free
    __shared__ __align__(16) float Ws[16][72];    // [k][n],  pad

    if (blockIdx.x < GEMM_BLKS) {
        int tid = threadIdx.x;
        int lane = tid & 31;
        int gid = lane >> 2, tig = lane & 3;
        int m0 = (tid >> 5) * 16;
        int n0 = blockIdx.x * 128;

        float acc[8][4];
        #pragma unroll
        for (int nt = 0; nt < 8; nt++)
            #pragma unroll
            for (int r = 0; r < 4; r++) acc[nt][r] = 0.f;

        for (int k0 = 0; k0 < FF; k0 += 16) {
            #pragma unroll
            for (int r = 0; r < 2; r++) {
                int v = tid + r * 256;
                int row = v >> 2, kq = v & 3;
                int gn = n0 + row;
                float4 xv = make_float4(0.f, 0.f, 0.f, 0.f);
                if (gn < NN) xv = *(const float4*)(X + (size_t)gn * FF + k0 + kq * 4);
                Xs[kq * 4 + 0][row] = xv.x;
                Xs[kq * 4 + 1][row] = xv.y;
                Xs[kq * 4 + 2][row] = xv.z;
                Xs[kq * 4 + 3][row] = xv.w;
            }
            {
                int kk = tid >> 4, nq = tid & 15;
                float4 wv = *(const float4*)(g_w1t + (size_t)(k0 + kk) * HH + nq * 4);
                Ws[kk][nq * 4 + 0] = wv.x;
                Ws[kk][nq * 4 + 1] = wv.y;
                Ws[kk][nq * 4 + 2] = wv.z;
                Ws[kk][nq * 4 + 3] = wv.w;
            }
            __syncthreads();
            #pragma unroll
            for (int ks = 0; ks < 2; ks++) {
                unsigned a[4];
                a[0] = f2tf32(Xs[ks * 8 + tig    ][m0 + gid    ]);
                a[1] = f2tf32(Xs[ks * 8 + tig    ][m0 + gid + 8]);
                a[2] = f2tf32(Xs[ks * 8 + tig + 4][m0 + gid    ]);
                a[3] = f2tf32(Xs[ks * 8 + tig + 4][m0 + gid + 8]);
                #pragma unroll
                for (int nt = 0; nt < 8; nt++) {
                    unsigned b[2];
                    b[0] = __float_as_uint(Ws[ks * 8 + tig    ][nt * 8 + gid]);
                    b[1] = __float_as_uint(Ws[ks * 8 + tig + 4][nt * 8 + gid]);
                    mma_tf32(acc[nt], a, b);
                }
            }
            __syncthreads();
        }

        // simple epilogue: bias + relu -> g_hidden (round-2 proven, no spills)
        #pragma unroll
        for (int rr = 0; rr < 2; rr++) {
            int row = n0 + m0 + rr * 8 + gid;
            if (row >= NN) continue;
            #pragma unroll
            for (int nt = 0; nt < 8; nt++) {
                int col = nt * 8 + 2 * tig;
                float v0 = fmaxf(acc[nt][rr * 2 + 0] + bias[col], 0.f);
                float v1 = fmaxf(acc[nt][rr * 2 + 1] + bias[col + 1], 0.f);
                *(float2*)(g_hidden + (size_t)row * HH + col) = make_float2(v0, v1);
            }
        }
        return;
    }

    // ---- CSR scatter branch (bitmask + x4 vectorized, 8B records) ----
    int t = (blockIdx.x - GEMM_BLKS) * 256 + threadIdx.x;   // covers 4 edges
    int4   s4 = ((const int4*)src)[t];
    int4   d4 = ((const int4*)dst)[t];
    float4 e0 = ((const float4*)e_edge)[t];
    float4 e1 = ((const float4*)(e_edge + 2 * (size_t)EE))[t];
    int base = ((t << 2) >= EE) ? NN : 0;
    // softmax max-shift cancels; exp(|e|<6) safe; fp16 range ok (exp<=e^6~403)
    if (!is_train(d4.x)) {
        int p = atomicAdd(&g_wp[base + d4.x], 1);
        __half2 w = __floats2half2_rn(__expf(e0.x), __expf(e1.x));
        g_edge8[p] = make_uint2((unsigned)s4.x, *(unsigned*)&w);
    }
    if (!is_train(d4.y)) {
        int p = atomicAdd(&g_wp[base + d4.y], 1);
        __half2 w = __floats2half2_rn(__expf(e0.y), __expf(e1.y));
        g_edge8[p] = make_uint2((unsigned)s4.y, *(unsigned*)&w);
    }
    if (!is_train(d4.z)) {
        int p = atomicAdd(&g_wp[base + d4.z], 1);
        __half2 w = __floats2half2_rn(__expf(e0.z), __expf(e1.z));
        g_edge8[p] = make_uint2((unsigned)s4.z, *(unsigned*)&w);
    }
    if (!is_train(d4.w)) {
        int p = atomicAdd(&g_wp[base + d4.w], 1);
        __half2 w = __floats2half2_rn(__expf(e0.w), __expf(e1.w));
        g_edge8[p] = make_uint2((unsigned)s4.w, *(unsigned*)&w);
    }
}

// ---------------- propagate (gather, warp-per-vnode, 2 lanes/edge, fp16 h) --
template <int LAYER>
__global__ __launch_bounds__(256) void prop_kernel(const float* __restrict__ one_hot) {
    int v    = (blockIdx.x * blockDim.x + threadIdx.x) >> 5;
    int lane = threadIdx.x & 31;
    if (v >= VN) return;
    int n = (v < NN) ? v : v - NN;

    if (is_train(n)) {
        if (LAYER == 0) {
            if (lane < 2) g_h016[(size_t)v * 2 + lane] = g_oh16[(size_t)n * 2 + lane];
        } else {
            if (lane < CC) g_hg[(size_t)v * CC + lane] = one_hot[(size_t)n * CC + lane];
        }
        return;
    }

    const uint4* hbase = (LAYER == 0) ? g_li16
                                      : (g_h016 + ((v < NN) ? 0 : (size_t)NN * 2));
    int beg = g_rowptr[v], end = g_rowptr[v + 1];
    int half = lane & 1;                 // which 8-class half this lane owns

    float a[8];
    #pragma unroll
    for (int q = 0; q < 8; q++) a[q] = 0.f;
    float sw = 0.f;

    for (int j = beg + (lane >> 1); j < end; j += 16) {
        uint2 rec = g_edge8[j];
        int s = (int)rec.x;
        __half2 wh = *(__half2*)&rec.y;
        float w = (LAYER == 0) ? __low2float(wh) : __high2float(wh);
        uint4 u = hbase[(size_t)s * 2 + half];
        float2 f0 = __half22float2(*(__half2*)&u.x);
        float2 f1 = __half22float2(*(__half2*)&u.y);
        float2 f2 = __half22float2(*(__half2*)&u.z);
        float2 f3 = __half22float2(*(__half2*)&u.w);
        a[0] = fmaf(w, f0.x, a[0]); a[1] = fmaf(w, f0.y, a[1]);
        a[2] = fmaf(w, f1.x, a[2]); a[3] = fmaf(w, f1.y, a[3]);
        a[4] = fmaf(w, f2.x, a[4]); a[5] = fmaf(w, f2.y, a[5]);
        a[6] = fmaf(w, f3.x, a[6]); a[7] = fmaf(w, f3.y, a[7]);
        sw += w;
    }
    #pragma unroll
    for (int off = 2; off < 32; off <<= 1) {
        #pragma unroll
        for (int q = 0; q < 8; q++)
            a[q] += __shfl_xor_sync(0xFFFFFFFFu, a[q], off);
        sw += __shfl_xor_sync(0xFFFFFFFFu, sw, off);
    }
    if (lane < 2) {
        float inv = (sw > 0.f) ? (1.f / sw) : 0.f;
        #pragma unroll
        for (int q = 0; q < 8; q++) a[q] *= inv;
        if (LAYER == 0) {
            __half2 o0 = __floats2half2_rn(a[0], a[1]);
            __half2 o1 = __floats2half2_rn(a[2], a[3]);
            __half2 o2 = __floats2half2_rn(a[4], a[5]);
            __half2 o3 = __floats2half2_rn(a[6], a[7]);
            uint4 u;
            u.x = *(unsigned*)&o0; u.y = *(unsigned*)&o1;
            u.z = *(unsigned*)&o2; u.w = *(unsigned*)&o3;
            g_h016[(size_t)v * 2 + half] = u;
        } else {
            float* op = g_hg + (size_t)v * CC + half * 8;
            ((float4*)op)[0] = make_float4(a[0], a[1], a[2], a[3]);
            ((float4*)op)[1] = make_float4(a[4], a[5], a[6], a[7]);
        }
    }
}

// ---------------- final: MLP layer 2 + attention combine + output -----------
__global__ __launch_bounds__(256) void final_kernel(const float* __restrict__ w2,
                                                    const float* __restrict__ b2,
                                                    const float* __restrict__ att,
                                                    const float* __restrict__ alpha,
                                                    float* __restrict__ out) {
    __shared__ float sw2[HH * CC];
    for (int i = threadIdx.x; i < HH * CC; i += blockDim.x) sw2[i] = w2[i];
    __syncthreads();
    int idx = blockIdx.x * blockDim.x + threadIdx.x;
    if (idx >= NN * CC) return;
    int n = idx >> 4, c = idx & 15;

    float m = b2[c];
    const float4* hr = (const float4*)(g_hidden + (size_t)n * HH);
    #pragma unroll
    for (int k = 0; k < 16; k++) {
        float4 hv = hr[k];
        m = fmaf(hv.x, sw2[(4 * k + 0) * CC + c], m);
        m = fmaf(hv.y, sw2[(4 * k + 1) * CC + c], m);
        m = fmaf(hv.z, sw2[(4 * k + 2) * CC + c], m);
        m = fmaf(hv.w, sw2[(4 * k + 3) * CC + c], m);
    }

    float a0 = att[n * 2 + 0], a1 = att[n * 2 + 1];
    float mx = fmaxf(a0, a1);
    float e0 = expf(a0 - mx), e1 = expf(a1 - mx);
    float inv = 1.f / (e0 + e1);

    float sa = 1.f / (1.f + expf(-alpha[n]));
    float logits = g_hg[idx] * (e0 * inv) + g_hg[(size_t)(NN + n) * CC + c] * (e1 * inv);
    out[idx] = sa * logits + (1.f - sa) * m;
}

// ---------------- launcher ----------------
extern "C" void kernel_launch(void* const* d_in, const int* in_sizes, int n_in,
                              void* d_out, int out_size) {
    (void)in_sizes; (void)n_in; (void)out_size;
    const float* features   = (const float*)d_in[0];
    const float* label_init = (const float*)d_in[1];
    const float* one_hot    = (const float*)d_in[2];
    const float* alpha      = (const float*)d_in[3];
    const float* attention  = (const float*)d_in[4];
    const float* e_edge     = (const float*)d_in[5];
    const float* w1         = (const float*)d_in[6];
    const float* b1         = (const float*)d_in[7];
    const float* w2         = (const float*)d_in[8];
    const float* b2         = (const float*)d_in[9];
    const int*   src        = (const int*)d_in[10];
    const int*   dst        = (const int*)d_in[11];
    const int*   train      = (const int*)d_in[12];
    float*       out        = (float*)d_out;

    void* cnt_ptr = nullptr;
    cudaGetSymbolAddress(&cnt_ptr, g_cnt);
    cudaMemsetAsync(cnt_ptr, 0, VN * sizeof(int));

    prep_kernel<<<(NN * CC / 2 + 255) / 256, 256>>>(train, w1, label_init, one_hot); // 1
    hist_kernel<<<EB4, 256>>>(dst);                                                  // 2
    scan1_kernel<<<NBLK2, 1024>>>();                                                 // 3
    scan23_kernel<<<NBLK2, 1024>>>();                                                // 4 (ncu)
    scatter_gemm_kernel<<<GEMM_BLKS + EB4, 256>>>(src, dst, e_edge, features, b1);   // 5
    prop_kernel<0><<<PB2, 256>>>(one_hot);                                           // 6
    prop_kernel<1><<<PB2, 256>>>(one_hot);                                           // 7
    final_kernel<<<FB, 256>>>(w2, b2, attention, alpha, out);                        // 8
}

// round 8
// speedup vs baseline: 1.5915x; 1.0186x over previous
#include <cuda_runtime.h>
#include <cuda_fp16.h>
#include <math.h>

#define NN 100000
#define CC 16
#define EE 3200000
#define FF 512
#define HH 64
#define VN (2*NN)

#define NBLK2 196        // ceil(VN/1024)
#define EB4   6250       // 2*EE/(256*4)
#define PB2   25000      // VN warps / 8 warps-per-block
#define FB    6250       // NN*CC/256
#define GEMM_BLKS 782    // ceil(NN/128)
#define MASKW 3125       // NN/32

// ---------------- scratch (device globals: allocation-free) ----------------
__device__ int      g_cnt[VN];
__device__ int      g_tmpscan[VN];
__device__ int      g_rowptr[VN + 1];
__device__ int      g_wp[VN];
__device__ int      g_blksum[256];
__device__ unsigned g_trainbit[MASKW];
__device__ uint2    g_edge8[2 * EE];       // {src, half2(exp(e_l0), exp(e_l1))}
__device__ uint4    g_li16[NN * 2];        // label_init fp16 (2 uint4 = 16 halves/row)
__device__ uint4    g_oh16[NN * 2];        // one_hot fp16
__device__ uint4    g_h016[VN * 2];        // layer-0 output fp16, both graphs
__device__ float    g_hg[VN * CC];         // layer-1 output fp32, both graphs
__device__ float    g_hidden[NN * HH];     // MLP hidden (relu(X@W1+b1))
__device__ __half   g_w1h[HH * FF];        // W1 transposed [n][k], fp16

// ---------------- helpers ----------------
__device__ __forceinline__ void mma_f16(float c[4], unsigned a0, unsigned a1,
                                        unsigned a2, unsigned a3,
                                        unsigned b0, unsigned b1) {
    asm volatile("mma.sync.aligned.m16n8k16.row.col.f32.f16.f16.f32 "
                 "{%0,%1,%2,%3}, {%4,%5,%6,%7}, {%8,%9}, {%0,%1,%2,%3};"
                 : "+f"(c[0]), "+f"(c[1]), "+f"(c[2]), "+f"(c[3])
                 : "r"(a0), "r"(a1), "r"(a2), "r"(a3), "r"(b0), "r"(b1));
}
__device__ __forceinline__ bool is_train(int d) {
    return (g_trainbit[d >> 5] >> (d & 31)) & 1u;
}

// ---------------- prep: bitmask + W1 fp16 transpose + fp16 conversions ------
__global__ __launch_bounds__(256) void prep_kernel(const int* __restrict__ train,
                                                   const float* __restrict__ w1,
                                                   const float* __restrict__ label_init,
                                                   const float* __restrict__ one_hot) {
    int i = blockIdx.x * blockDim.x + threadIdx.x;     // grid covers NN*CC/2 = 800000
    if (i < NN * CC / 2) {
        float2 li = ((const float2*)label_init)[i];
        float2 oh = ((const float2*)one_hot)[i];
        __half2 l2 = __floats2half2_rn(li.x, li.y);
        __half2 o2 = __floats2half2_rn(oh.x, oh.y);
        ((unsigned*)g_li16)[i] = *(unsigned*)&l2;
        ((unsigned*)g_oh16)[i] = *(unsigned*)&o2;
    }
    if (i < FF * HH) {
        int k = i >> 6, n = i & 63;                    // w1 is [k][n], HH=64
        g_w1h[n * FF + k] = __float2half(w1[i]);
    }
    if (i < VN) g_cnt[i] = 0;
    if (i < MASKW) {
        unsigned m = 0;
        #pragma unroll 8
        for (int b = 0; b < 32; b++)
            m |= (train[i * 32 + b] != 0 ? 1u : 0u) << b;
        g_trainbit[i] = m;
    }
}

// ---------------- hist (bitmask + int4 vectorized) --------------------------
__global__ __launch_bounds__(256) void hist_kernel(const int* __restrict__ dst) {
    int t = blockIdx.x * 256 + threadIdx.x;            // covers 4 edges
    int4 d4 = ((const int4*)dst)[t];
    int base = ((t << 2) >= EE) ? NN : 0;              // EE % 4 == 0
    if (!is_train(d4.x)) atomicAdd(&g_cnt[base + d4.x], 1);
    if (!is_train(d4.y)) atomicAdd(&g_cnt[base + d4.y], 1);
    if (!is_train(d4.z)) atomicAdd(&g_cnt[base + d4.z], 1);
    if (!is_train(d4.w)) atomicAdd(&g_cnt[base + d4.w], 1);
}

// ---------------- scan stage 1 ----------------
__global__ __launch_bounds__(1024) void scan1_kernel() {
    __shared__ int s[1024];
    int i = blockIdx.x * 1024 + threadIdx.x;
    int v = (i < VN) ? g_cnt[i] : 0;
    s[threadIdx.x] = v;
    __syncthreads();
    #pragma unroll
    for (int off = 1; off < 1024; off <<= 1) {
        int t = (threadIdx.x >= off) ? s[threadIdx.x - off] : 0;
        __syncthreads();
        s[threadIdx.x] += t;
        __syncthreads();
    }
    if (i < VN) g_tmpscan[i] = s[threadIdx.x];
    if (threadIdx.x == 1023) g_blksum[blockIdx.x] = s[1023];
}

// ---------------- scan stage 2 (block-offset scan inlined per block) --------
__global__ __launch_bounds__(1024) void scan23_kernel() {
    __shared__ int s2[256];
    int t = threadIdx.x;
    int v2 = 0;
    if (t < 256) {
        v2 = (t < NBLK2) ? g_blksum[t] : 0;
        s2[t] = v2;
    }
    __syncthreads();
    #pragma unroll
    for (int off = 1; off < 256; off <<= 1) {
        int u = 0;
        if (t < 256 && t >= off) u = s2[t - off];
        __syncthreads();
        if (t < 256) s2[t] += u;
        __syncthreads();
    }
    if (t < 256) s2[t] -= v2;                          // exclusive
    __syncthreads();

    int i = blockIdx.x * 1024 + t;
    if (i < VN) {
        int incl = g_tmpscan[i] + s2[blockIdx.x];
        g_rowptr[i + 1] = incl;
        g_wp[i] = incl - g_cnt[i];
    }
    if (i == 0) g_rowptr[0] = 0;
}

// ---------------- fused: fp16 GEMM (blocks < GEMM_BLKS) + CSR scatter -------
// GEMM: relu(X[N,512]@W1+b1) -> g_hidden, fp16 mma m16n8k16, fp32 accumulate.
__global__ __launch_bounds__(256) void scatter_gemm_kernel(
        const int* __restrict__ src, const int* __restrict__ dst,
        const float* __restrict__ e_edge,
        const float* __restrict__ X, const float* __restrict__ bias) {
    __shared__ __align__(16) __half Xs[128][24];   // [row][k], stride 48B: conflict-free
    __shared__ __align__(16) __half Ws[64][24];    // [n][k]

    if (blockIdx.x < GEMM_BLKS) {
        int tid = threadIdx.x;
        int lane = tid & 31;
        int gid = lane >> 2, tig = lane & 3;
        int m0 = (tid >> 5) * 16;
        int n0 = blockIdx.x * 128;

        float acc[8][4];
        #pragma unroll
        for (int nt = 0; nt < 8; nt++)
            #pragma unroll
            for (int r = 0; r < 4; r++) acc[nt][r] = 0.f;

        for (int k0 = 0; k0 < FF; k0 += 16) {
            // stage X tile (128 rows x 16 k) as fp16 [row][k]
            #pragma unroll
            for (int r = 0; r < 2; r++) {
                int idx = tid + r * 256;               // 0..511
                int row = idx >> 2, kq = idx & 3;
                int gn = n0 + row;
                float4 xv = make_float4(0.f, 0.f, 0.f, 0.f);
                if (gn < NN) xv = *(const float4*)(X + (size_t)gn * FF + k0 + kq * 4);
                __half2 h0 = __floats2half2_rn(xv.x, xv.y);
                __half2 h1 = __floats2half2_rn(xv.z, xv.w);
                *(uint2*)&Xs[row][kq * 4] = make_uint2(*(unsigned*)&h0, *(unsigned*)&h1);
            }
            // stage W tile (64 n x 16 k), already fp16 transposed
            if (tid < 128) {
                int row = tid >> 1, part = tid & 1;
                uint4 wv = *(const uint4*)(g_w1h + (size_t)row * FF + k0 + part * 8);
                *(uint4*)&Ws[row][part * 8] = wv;
            }
            __syncthreads();
            unsigned a0 = *(unsigned*)&Xs[m0 + gid    ][2 * tig    ];
            unsigned a1 = *(unsigned*)&Xs[m0 + gid + 8][2 * tig    ];
            unsigned a2 = *(unsigned*)&Xs[m0 + gid    ][2 * tig + 8];
            unsigned a3 = *(unsigned*)&Xs[m0 + gid + 8][2 * tig + 8];
            #pragma unroll
            for (int nt = 0; nt < 8; nt++) {
                unsigned b0 = *(unsigned*)&Ws[nt * 8 + gid][2 * tig    ];
                unsigned b1 = *(unsigned*)&Ws[nt * 8 + gid][2 * tig + 8];
                mma_f16(acc[nt], a0, a1, a2, a3, b0, b1);
            }
            __syncthreads();
        }

        // simple epilogue: bias + relu -> g_hidden
        #pragma unroll
        for (int rr = 0; rr < 2; rr++) {
            int row = n0 + m0 + rr * 8 + gid;
            if (row >= NN) continue;
            #pragma unroll
            for (int nt = 0; nt < 8; nt++) {
                int col = nt * 8 + 2 * tig;
                float v0 = fmaxf(acc[nt][rr * 2 + 0] + bias[col], 0.f);
                float v1 = fmaxf(acc[nt][rr * 2 + 1] + bias[col + 1], 0.f);
                *(float2*)(g_hidden + (size_t)row * HH + col) = make_float2(v0, v1);
            }
        }
        return;
    }

    // ---- CSR scatter branch (bitmask + x4 vectorized, 8B records) ----
    int t = (blockIdx.x - GEMM_BLKS) * 256 + threadIdx.x;   // covers 4 edges
    int4   s4 = ((const int4*)src)[t];
    int4   d4 = ((const int4*)dst)[t];
    float4 e0 = ((const float4*)e_edge)[t];
    float4 e1 = ((const float4*)(e_edge + 2 * (size_t)EE))[t];
    int base = ((t << 2) >= EE) ? NN : 0;
    // softmax max-shift cancels; exp(|e|<6) safe; fp16 range ok (exp<=e^6~403)
    if (!is_train(d4.x)) {
        int p = atomicAdd(&g_wp[base + d4.x], 1);
        __half2 w = __floats2half2_rn(__expf(e0.x), __expf(e1.x));
        g_edge8[p] = make_uint2((unsigned)s4.x, *(unsigned*)&w);
    }
    if (!is_train(d4.y)) {
        int p = atomicAdd(&g_wp[base + d4.y], 1);
        __half2 w = __floats2half2_rn(__expf(e0.y), __expf(e1.y));
        g_edge8[p] = make_uint2((unsigned)s4.y, *(unsigned*)&w);
    }
    if (!is_train(d4.z)) {
        int p = atomicAdd(&g_wp[base + d4.z], 1);
        __half2 w = __floats2half2_rn(__expf(e0.z), __expf(e1.z));
        g_edge8[p] = make_uint2((unsigned)s4.z, *(unsigned*)&w);
    }
    if (!is_train(d4.w)) {
        int p = atomicAdd(&g_wp[base + d4.w], 1);
        __half2 w = __floats2half2_rn(__expf(e0.w), __expf(e1.w));
        g_edge8[p] = make_uint2((unsigned)s4.w, *(unsigned*)&w);
    }
}

// ---- propagate (gather, warp-per-vnode, 2 lanes/edge, dual-edge MLP) -------
template <int LAYER>
__global__ __launch_bounds__(256) void prop_kernel(const float* __restrict__ one_hot) {
    int v    = (blockIdx.x * blockDim.x + threadIdx.x) >> 5;
    int lane = threadIdx.x & 31;
    if (v >= VN) return;
    int n = (v < NN) ? v : v - NN;

    if (is_train(n)) {
        if (LAYER == 0) {
            if (lane < 2) g_h016[(size_t)v * 2 + lane] = g_oh16[(size_t)n * 2 + lane];
        } else {
            if (lane < CC) g_hg[(size_t)v * CC + lane] = one_hot[(size_t)n * CC + lane];
        }
        return;
    }

    const uint4* hbase = (LAYER == 0) ? g_li16
                                      : (g_h016 + ((v < NN) ? 0 : (size_t)NN * 2));
    int beg = g_rowptr[v], end = g_rowptr[v + 1];
    int half = lane & 1;                 // which 8-class half this lane owns

    float a[8];
    #pragma unroll
    for (int q = 0; q < 8; q++) a[q] = 0.f;
    float sw = 0.f;

    // two edges in flight per lane-pair: j and j+16 (avg degree 32 -> 1 iter)
    for (int j = beg + (lane >> 1); j < end; j += 32) {
        uint2 r1 = g_edge8[j];
        int j2 = j + 16;
        uint2 r2 = (j2 < end) ? g_edge8[j2] : make_uint2(r1.x, 0u);  // w=0 pad
        int s1 = (int)r1.x, s2 = (int)r2.x;
        __half2 wh1 = *(__half2*)&r1.y, wh2 = *(__half2*)&r2.y;
        float w1 = (LAYER == 0) ? __low2float(wh1) : __high2float(wh1);
        float w2 = (LAYER == 0) ? __low2float(wh2) : __high2float(wh2);
        uint4 u1 = hbase[(size_t)s1 * 2 + half];
        uint4 u2 = hbase[(size_t)s2 * 2 + half];
        {
            float2 f0 = __half22float2(*(__half2*)&u1.x);
            float2 f1 = __half22float2(*(__half2*)&u1.y);
            float2 f2 = __half22float2(*(__half2*)&u1.z);
            float2 f3 = __half22float2(*(__half2*)&u1.w);
            a[0] = fmaf(w1, f0.x, a[0]); a[1] = fmaf(w1, f0.y, a[1]);
            a[2] = fmaf(w1, f1.x, a[2]); a[3] = fmaf(w1, f1.y, a[3]);
            a[4] = fmaf(w1, f2.x, a[4]); a[5] = fmaf(w1, f2.y, a[5]);
            a[6] = fmaf(w1, f3.x, a[6]); a[7] = fmaf(w1, f3.y, a[7]);
        }
        {
            float2 f0 = __half22float2(*(__half2*)&u2.x);
            float2 f1 = __half22float2(*(__half2*)&u2.y);
            float2 f2 = __half22float2(*(__half2*)&u2.z);
            float2 f3 = __half22float2(*(__half2*)&u2.w);
            a[0] = fmaf(w2, f0.x, a[0]); a[1] = fmaf(w2, f0.y, a[1]);
            a[2] = fmaf(w2, f1.x, a[2]); a[3] = fmaf(w2, f1.y, a[3]);
            a[4] = fmaf(w2, f2.x, a[4]); a[5] = fmaf(w2, f2.y, a[5]);
            a[6] = fmaf(w2, f3.x, a[6]); a[7] = fmaf(w2, f3.y, a[7]);
        }
        sw += w1 + w2;
    }
    #pragma unroll
    for (int off = 2; off < 32; off <<= 1) {
        #pragma unroll
        for (int q = 0; q < 8; q++)
            a[q] += __shfl_xor_sync(0xFFFFFFFFu, a[q], off);
        sw += __shfl_xor_sync(0xFFFFFFFFu, sw, off);
    }
    if (lane < 2) {
        float inv = (sw > 0.f) ? (1.f / sw) : 0.f;
        #pragma unroll
        for (int q = 0; q < 8; q++) a[q] *= inv;
        if (LAYER == 0) {
            __half2 o0 = __floats2half2_rn(a[0], a[1]);
            __half2 o1 = __floats2half2_rn(a[2], a[3]);
            __half2 o2 = __floats2half2_rn(a[4], a[5]);
            __half2 o3 = __floats2half2_rn(a[6], a[7]);
            uint4 u;
            u.x = *(unsigned*)&o0; u.y = *(unsigned*)&o1;
            u.z = *(unsigned*)&o2; u.w = *(unsigned*)&o3;
            g_h016[(size_t)v * 2 + half] = u;
        } else {
            float* op = g_hg + (size_t)v * CC + half * 8;
            ((float4*)op)[0] = make_float4(a[0], a[1], a[2], a[3]);
            ((float4*)op)[1] = make_float4(a[4], a[5], a[6], a[7]);
        }
    }
}

// ---------------- final: MLP layer 2 + attention combine + output -----------
__global__ __launch_bounds__(256) void final_kernel(const float* __restrict__ w2,
                                                    const float* __restrict__ b2,
                                                    const float* __restrict__ att,
                                                    const float* __restrict__ alpha,
                                                    float* __restrict__ out) {
    __shared__ float sw2[HH * CC];
    for (int i = threadIdx.x; i < HH * CC; i += blockDim.x) sw2[i] = w2[i];
    __syncthreads();
    int idx = blockIdx.x * blockDim.x + threadIdx.x;
    if (idx >= NN * CC) return;
    int n = idx >> 4, c = idx & 15;

    float m = b2[c];
    const float4* hr = (const float4*)(g_hidden + (size_t)n * HH);
    #pragma unroll
    for (int k = 0; k < 16; k++) {
        float4 hv = hr[k];
        m = fmaf(hv.x, sw2[(4 * k + 0) * CC + c], m);
        m = fmaf(hv.y, sw2[(4 * k + 1) * CC + c], m);
        m = fmaf(hv.z, sw2[(4 * k + 2) * CC + c], m);
        m = fmaf(hv.w, sw2[(4 * k + 3) * CC + c], m);
    }

    float a0 = att[n * 2 + 0], a1 = att[n * 2 + 1];
    float mx = fmaxf(a0, a1);
    float e0 = expf(a0 - mx), e1 = expf(a1 - mx);
    float inv = 1.f / (e0 + e1);

    float sa = 1.f / (1.f + expf(-alpha[n]));
    float logits = g_hg[idx] * (e0 * inv) + g_hg[(size_t)(NN + n) * CC + c] * (e1 * inv);
    out[idx] = sa * logits + (1.f - sa) * m;
}

// ---------------- launcher ----------------
extern "C" void kernel_launch(void* const* d_in, const int* in_sizes, int n_in,
                              void* d_out, int out_size) {
    (void)in_sizes; (void)n_in; (void)out_size;
    const float* features   = (const float*)d_in[0];
    const float* label_init = (const float*)d_in[1];
    const float* one_hot    = (const float*)d_in[2];
    const float* alpha      = (const float*)d_in[3];
    const float* attention  = (const float*)d_in[4];
    const float* e_edge     = (const float*)d_in[5];
    const float* w1         = (const float*)d_in[6];
    const float* b1         = (const float*)d_in[7];
    const float* w2         = (const float*)d_in[8];
    const float* b2         = (const float*)d_in[9];
    const int*   src        = (const int*)d_in[10];
    const int*   dst        = (const int*)d_in[11];
    const int*   train      = (const int*)d_in[12];
    float*       out        = (float*)d_out;

    prep_kernel<<<(NN * CC / 2 + 255) / 256, 256>>>(train, w1, label_init, one_hot); // 1
    hist_kernel<<<EB4, 256>>>(dst);                                                  // 2
    scan1_kernel<<<NBLK2, 1024>>>();                                                 // 3
    scan23_kernel<<<NBLK2, 1024>>>();                                                // 4
    scatter_gemm_kernel<<<GEMM_BLKS + EB4, 256>>>(src, dst, e_edge, features, b1);   // 5
    prop_kernel<0><<<PB2, 256>>>(one_hot);                                           // 6
    prop_kernel<1><<<PB2, 256>>>(one_hot);                                           // 7
    final_kernel<<<FB, 256>>>(w2, b2, attention, alpha, out);                        // 8
}

// round 9
// speedup vs baseline: 1.6024x; 1.0069x over previous
#include <cuda_runtime.h>
#include <cuda_fp16.h>
#include <math.h>

#define NN 100000
#define CC 16
#define EE 3200000
#define FF 512
#define HH 64
#define VN (2*NN)

#define NBLK2 196        // ceil(VN/1024)
#define EB4   6250       // 2*EE/(256*4)
#define PB2   25000      // VN warps / 8 warps-per-block
#define FB    6250       // NN*CC/256
#define GEMM_BLKS 782    // ceil(NN/128)
#define MASKW 3125       // NN/32

// ---------------- scratch (device globals: allocation-free) ----------------
__device__ int      g_cnt[VN];
__device__ int      g_rowptr[VN + 1];
__device__ int      g_wp[VN];
__device__ int      g_blksum[256];
__device__ int      g_arrive;
__device__ unsigned g_trainbit[MASKW];
__device__ uint2    g_edge8[2 * EE];       // {src, half2(exp(e_l0), exp(e_l1))}
__device__ uint4    g_li16[NN * 2];        // label_init fp16 (2 uint4 = 16 halves/row)
__device__ uint4    g_oh16[NN * 2];        // one_hot fp16
__device__ uint4    g_h016[VN * 2];        // layer-0 output fp16, both graphs
__device__ float    g_hg[VN * CC];         // layer-1 output fp32, both graphs
__device__ float    g_hidden[NN * HH];     // MLP hidden (relu(X@W1+b1))
__device__ __half   g_w1h[HH * FF];        // W1 transposed [n][k], fp16

// ---------------- helpers ----------------
__device__ __forceinline__ void mma_f16(float c[4], unsigned a0, unsigned a1,
                                        unsigned a2, unsigned a3,
                                        unsigned b0, unsigned b1) {
    asm volatile("mma.sync.aligned.m16n8k16.row.col.f32.f16.f16.f32 "
                 "{%0,%1,%2,%3}, {%4,%5,%6,%7}, {%8,%9}, {%0,%1,%2,%3};"
                 : "+f"(c[0]), "+f"(c[1]), "+f"(c[2]), "+f"(c[3])
                 : "r"(a0), "r"(a1), "r"(a2), "r"(a3), "r"(b0), "r"(b1));
}
__device__ __forceinline__ bool is_train(int d) {
    return (g_trainbit[d >> 5] >> (d & 31)) & 1u;
}

// ---------------- prep: bitmask + W1 fp16 transpose + fp16 conversions ------
__global__ __launch_bounds__(256) void prep_kernel(const int* __restrict__ train,
                                                   const float* __restrict__ w1,
                                                   const float* __restrict__ label_init,
                                                   const float* __restrict__ one_hot) {
    int i = blockIdx.x * blockDim.x + threadIdx.x;     // grid covers NN*CC/2 = 800000
    if (i < NN * CC / 2) {
        float2 li = ((const float2*)label_init)[i];
        float2 oh = ((const float2*)one_hot)[i];
        __half2 l2 = __floats2half2_rn(li.x, li.y);
        __half2 o2 = __floats2half2_rn(oh.x, oh.y);
        ((unsigned*)g_li16)[i] = *(unsigned*)&l2;
        ((unsigned*)g_oh16)[i] = *(unsigned*)&o2;
    }
    if (i < FF * HH) {
        int k = i >> 6, n = i & 63;                    // w1 is [k][n], HH=64
        g_w1h[n * FF + k] = __float2half(w1[i]);
    }
    if (i < VN) g_cnt[i] = 0;
    if (i == 0) g_arrive = 0;
    if (i < MASKW) {
        unsigned m = 0;
        #pragma unroll 8
        for (int b = 0; b < 32; b++)
            m |= (train[i * 32 + b] != 0 ? 1u : 0u) << b;
        g_trainbit[i] = m;
    }
}

// ---------------- hist (bitmask + int4 vectorized) --------------------------
__global__ __launch_bounds__(256) void hist_kernel(const int* __restrict__ dst) {
    int t = blockIdx.x * 256 + threadIdx.x;            // covers 4 edges
    int4 d4 = ((const int4*)dst)[t];
    int base = ((t << 2) >= EE) ? NN : 0;              // EE % 4 == 0
    if (!is_train(d4.x)) atomicAdd(&g_cnt[base + d4.x], 1);
    if (!is_train(d4.y)) atomicAdd(&g_cnt[base + d4.y], 1);
    if (!is_train(d4.z)) atomicAdd(&g_cnt[base + d4.z], 1);
    if (!is_train(d4.w)) atomicAdd(&g_cnt[base + d4.w], 1);
}

// ---------------- single-launch scan (grid barrier; 196 blocks all resident)
__global__ __launch_bounds__(1024) void scan_fused_kernel() {
    __shared__ int warpsum[32];
    __shared__ int s2[256];
    int b = blockIdx.x, t = threadIdx.x;
    int lane = t & 31, wid = t >> 5;
    int i = b * 1024 + t;
    int c = (i < VN) ? g_cnt[i] : 0;

    // warp-level inclusive scan
    int v = c;
    #pragma unroll
    for (int off = 1; off < 32; off <<= 1) {
        int u = __shfl_up_sync(0xFFFFFFFFu, v, off);
        if (lane >= off) v += u;
    }
    if (lane == 31) warpsum[wid] = v;
    __syncthreads();
    if (wid == 0) {
        int wv = warpsum[lane];
        #pragma unroll
        for (int off = 1; off < 32; off <<= 1) {
            int u = __shfl_up_sync(0xFFFFFFFFu, wv, off);
            if (lane >= off) wv += u;
        }
        warpsum[lane] = wv;
    }
    __syncthreads();
    int incl_local = v + ((wid > 0) ? warpsum[wid - 1] : 0);
    int total = warpsum[31];

    // publish block total, grid barrier (all 196 blocks are resident: safe)
    if (t == 0) {
        g_blksum[b] = total;
        __threadfence();
        atomicAdd(&g_arrive, 1);
        while (atomicAdd(&g_arrive, 0) < NBLK2) { }
    }
    __syncthreads();

    // exclusive prefix over block sums (inclusive scan, then shift via b-1)
    if (t < 256) s2[t] = (t < NBLK2) ? g_blksum[t] : 0;
    __syncthreads();
    #pragma unroll
    for (int off = 1; off < 256; off <<= 1) {
        int u = 0;
        if (t < 256 && t >= off) u = s2[t - off];
        __syncthreads();
        if (t < 256) s2[t] += u;
        __syncthreads();
    }
    int prev = (b > 0) ? s2[b - 1] : 0;
    if (i < VN) {
        int incl = incl_local + prev;
        g_rowptr[i + 1] = incl;
        g_wp[i] = incl - c;
    }
    if (i == 0) g_rowptr[0] = 0;
}

// ---------------- fused: fp16 GEMM (reg-prefetch pipeline) + CSR scatter ----
__global__ __launch_bounds__(256) void scatter_gemm_kernel(
        const int* __restrict__ src, const int* __restrict__ dst,
        const float* __restrict__ e_edge,
        const float* __restrict__ X, const float* __restrict__ bias) {
    __shared__ __align__(16) __half Xs[128][24];   // [row][k], 48B stride: conflict-free
    __shared__ __align__(16) __half Ws[64][24];    // [n][k]

    if (blockIdx.x < GEMM_BLKS) {
        int tid = threadIdx.x;
        int lane = tid & 31;
        int gid = lane >> 2, tig = lane & 3;
        int m0 = (tid >> 5) * 16;
        int n0 = blockIdx.x * 128;

        // per-thread staging roles
        int xrow0 = (tid          ) >> 2, xkq0 = tid & 3;
        int xrow1 = (tid + 256    ) >> 2, xkq1 = xkq0;
        int wrow  = tid >> 1,             wpart = tid & 1;

        float acc[8][4];
        #pragma unroll
        for (int nt = 0; nt < 8; nt++)
            #pragma unroll
            for (int r = 0; r < 4; r++) acc[nt][r] = 0.f;

        float4 xr0, xr1; uint4 wr;
        // prologue: load tile 0
        {
            int gn0 = n0 + xrow0, gn1 = n0 + xrow1;
            xr0 = (gn0 < NN) ? *(const float4*)(X + (size_t)gn0 * FF + xkq0 * 4)
                             : make_float4(0.f, 0.f, 0.f, 0.f);
            xr1 = (gn1 < NN) ? *(const float4*)(X + (size_t)gn1 * FF + xkq1 * 4)
                             : make_float4(0.f, 0.f, 0.f, 0.f);
            if (tid < 128) wr = *(const uint4*)(g_w1h + (size_t)wrow * FF + wpart * 8);
        }
        #pragma unroll 1
        for (int k0 = 0; k0 < FF; k0 += 16) {
            // store current regs to smem
            {
                __half2 h0 = __floats2half2_rn(xr0.x, xr0.y);
                __half2 h1 = __floats2half2_rn(xr0.z, xr0.w);
                *(uint2*)&Xs[xrow0][xkq0 * 4] = make_uint2(*(unsigned*)&h0, *(unsigned*)&h1);
                h0 = __floats2half2_rn(xr1.x, xr1.y);
                h1 = __floats2half2_rn(xr1.z, xr1.w);
                *(uint2*)&Xs[xrow1][xkq1 * 4] = make_uint2(*(unsigned*)&h0, *(unsigned*)&h1);
                if (tid < 128) *(uint4*)&Ws[wrow][wpart * 8] = wr;
            }
            __syncthreads();
            // prefetch next tile into regs (overlaps with MMA below)
            int kn = k0 + 16;
            if (kn < FF) {
                int gn0 = n0 + xrow0, gn1 = n0 + xrow1;
                xr0 = (gn0 < NN) ? *(const float4*)(X + (size_t)gn0 * FF + kn + xkq0 * 4)
                                 : make_float4(0.f, 0.f, 0.f, 0.f);
                xr1 = (gn1 < NN) ? *(const float4*)(X + (size_t)gn1 * FF + kn + xkq1 * 4)
                                 : make_float4(0.f, 0.f, 0.f, 0.f);
                if (tid < 128) wr = *(const uint4*)(g_w1h + (size_t)wrow * FF + kn + wpart * 8);
            }
            // MMA on current smem tile
            unsigned a0 = *(unsigned*)&Xs[m0 + gid    ][2 * tig    ];
            unsigned a1 = *(unsigned*)&Xs[m0 + gid + 8][2 * tig    ];
            unsigned a2 = *(unsigned*)&Xs[m0 + gid    ][2 * tig + 8];
            unsigned a3 = *(unsigned*)&Xs[m0 + gid + 8][2 * tig + 8];
            #pragma unroll
            for (int nt = 0; nt < 8; nt++) {
                unsigned b0 = *(unsigned*)&Ws[nt * 8 + gid][2 * tig    ];
                unsigned b1 = *(unsigned*)&Ws[nt * 8 + gid][2 * tig + 8];
                mma_f16(acc[nt], a0, a1, a2, a3, b0, b1);
            }
            __syncthreads();
        }

        // epilogue: bias + relu -> g_hidden
        #pragma unroll
        for (int rr = 0; rr < 2; rr++) {
            int row = n0 + m0 + rr * 8 + gid;
            if (row >= NN) continue;
            #pragma unroll
            for (int nt = 0; nt < 8; nt++) {
                int col = nt * 8 + 2 * tig;
                float v0 = fmaxf(acc[nt][rr * 2 + 0] + bias[col], 0.f);
                float v1 = fmaxf(acc[nt][rr * 2 + 1] + bias[col + 1], 0.f);
                *(float2*)(g_hidden + (size_t)row * HH + col) = make_float2(v0, v1);
            }
        }
        return;
    }

    // ---- CSR scatter branch (bitmask + x4 vectorized, 8B records) ----
    int t = (blockIdx.x - GEMM_BLKS) * 256 + threadIdx.x;   // covers 4 edges
    int4   s4 = ((const int4*)src)[t];
    int4   d4 = ((const int4*)dst)[t];
    float4 e0 = ((const float4*)e_edge)[t];
    float4 e1 = ((const float4*)(e_edge + 2 * (size_t)EE))[t];
    int base = ((t << 2) >= EE) ? NN : 0;
    // softmax max-shift cancels; exp(|e|<6) safe; fp16 range ok (exp<=e^6~403)
    if (!is_train(d4.x)) {
        int p = atomicAdd(&g_wp[base + d4.x], 1);
        __half2 w = __floats2half2_rn(__expf(e0.x), __expf(e1.x));
        g_edge8[p] = make_uint2((unsigned)s4.x, *(unsigned*)&w);
    }
    if (!is_train(d4.y)) {
        int p = atomicAdd(&g_wp[base + d4.y], 1);
        __half2 w = __floats2half2_rn(__expf(e0.y), __expf(e1.y));
        g_edge8[p] = make_uint2((unsigned)s4.y, *(unsigned*)&w);
    }
    if (!is_train(d4.z)) {
        int p = atomicAdd(&g_wp[base + d4.z], 1);
        __half2 w = __floats2half2_rn(__expf(e0.z), __expf(e1.z));
        g_edge8[p] = make_uint2((unsigned)s4.z, *(unsigned*)&w);
    }
    if (!is_train(d4.w)) {
        int p = atomicAdd(&g_wp[base + d4.w], 1);
        __half2 w = __floats2half2_rn(__expf(e0.w), __expf(e1.w));
        g_edge8[p] = make_uint2((unsigned)s4.w, *(unsigned*)&w);
    }
}

// ---- propagate (gather, warp-per-vnode, 2 lanes/edge, dual-edge MLP) -------
template <int LAYER>
__global__ __launch_bounds__(256) void prop_kernel(const float* __restrict__ one_hot) {
    int v    = (blockIdx.x * blockDim.x + threadIdx.x) >> 5;
    int lane = threadIdx.x & 31;
    if (v >= VN) return;
    int n = (v < NN) ? v : v - NN;

    if (is_train(n)) {
        if (LAYER == 0) {
            if (lane < 2) g_h016[(size_t)v * 2 + lane] = g_oh16[(size_t)n * 2 + lane];
        } else {
            if (lane < CC) g_hg[(size_t)v * CC + lane] = one_hot[(size_t)n * CC + lane];
        }
        return;
    }

    const uint4* hbase = (LAYER == 0) ? g_li16
                                      : (g_h016 + ((v < NN) ? 0 : (size_t)NN * 2));
    int beg = g_rowptr[v], end = g_rowptr[v + 1];
    int half = lane & 1;                 // which 8-class half this lane owns

    float a[8];
    #pragma unroll
    for (int q = 0; q < 8; q++) a[q] = 0.f;
    float sw = 0.f;

    // two edges in flight per lane-pair: j and j+16 (avg degree 32 -> 1 iter)
    for (int j = beg + (lane >> 1); j < end; j += 32) {
        uint2 r1 = g_edge8[j];
        int j2 = j + 16;
        uint2 r2 = (j2 < end) ? g_edge8[j2] : make_uint2(r1.x, 0u);  // w=0 pad
        int s1 = (int)r1.x, s2 = (int)r2.x;
        __half2 wh1 = *(__half2*)&r1.y, wh2 = *(__half2*)&r2.y;
        float w1 = (LAYER == 0) ? __low2float(wh1) : __high2float(wh1);
        float w2 = (LAYER == 0) ? __low2float(wh2) : __high2float(wh2);
        uint4 u1 = hbase[(size_t)s1 * 2 + half];
        uint4 u2 = hbase[(size_t)s2 * 2 + half];
        {
            float2 f0 = __half22float2(*(__half2*)&u1.x);
            float2 f1 = __half22float2(*(__half2*)&u1.y);
            float2 f2 = __half22float2(*(__half2*)&u1.z);
            float2 f3 = __half22float2(*(__half2*)&u1.w);
            a[0] = fmaf(w1, f0.x, a[0]); a[1] = fmaf(w1, f0.y, a[1]);
            a[2] = fmaf(w1, f1.x, a[2]); a[3] = fmaf(w1, f1.y, a[3]);
            a[4] = fmaf(w1, f2.x, a[4]); a[5] = fmaf(w1, f2.y, a[5]);
            a[6] = fmaf(w1, f3.x, a[6]); a[7] = fmaf(w1, f3.y, a[7]);
        }
        {
            float2 f0 = __half22float2(*(__half2*)&u2.x);
            float2 f1 = __half22float2(*(__half2*)&u2.y);
            float2 f2 = __half22float2(*(__half2*)&u2.z);
            float2 f3 = __half22float2(*(__half2*)&u2.w);
            a[0] = fmaf(w2, f0.x, a[0]); a[1] = fmaf(w2, f0.y, a[1]);
            a[2] = fmaf(w2, f1.x, a[2]); a[3] = fmaf(w2, f1.y, a[3]);
            a[4] = fmaf(w2, f2.x, a[4]); a[5] = fmaf(w2, f2.y, a[5]);
            a[6] = fmaf(w2, f3.x, a[6]); a[7] = fmaf(w2, f3.y, a[7]);
        }
        sw += w1 + w2;
    }
    #pragma unroll
    for (int off = 2; off < 32; off <<= 1) {
        #pragma unroll
        for (int q = 0; q < 8; q++)
            a[q] += __shfl_xor_sync(0xFFFFFFFFu, a[q], off);
        sw += __shfl_xor_sync(0xFFFFFFFFu, sw, off);
    }
    if (lane < 2) {
        float inv = (sw > 0.f) ? (1.f / sw) : 0.f;
        #pragma unroll
        for (int q = 0; q < 8; q++) a[q] *= inv;
        if (LAYER == 0) {
            __half2 o0 = __floats2half2_rn(a[0], a[1]);
            __half2 o1 = __floats2half2_rn(a[2], a[3]);
            __half2 o2 = __floats2half2_rn(a[4], a[5]);
            __half2 o3 = __floats2half2_rn(a[6], a[7]);
            uint4 u;
            u.x = *(unsigned*)&o0; u.y = *(unsigned*)&o1;
            u.z = *(unsigned*)&o2; u.w = *(unsigned*)&o3;
            g_h016[(size_t)v * 2 + half] = u;
        } else {
            float* op = g_hg + (size_t)v * CC + half * 8;
            ((float4*)op)[0] = make_float4(a[0], a[1], a[2], a[3]);
            ((float4*)op)[1] = make_float4(a[4], a[5], a[6], a[7]);
        }
    }
}

// ---------------- final: MLP layer 2 + attention combine + output -----------
__global__ __launch_bounds__(256) void final_kernel(const float* __restrict__ w2,
                                                    const float* __restrict__ b2,
                                                    const float* __restrict__ att,
                                                    const float* __restrict__ alpha,
                                                    float* __restrict__ out) {
    __shared__ float sw2[HH * CC];
    for (int i = threadIdx.x; i < HH * CC; i += blockDim.x) sw2[i] = w2[i];
    __syncthreads();
    int idx = blockIdx.x * blockDim.x + threadIdx.x;
    if (idx >= NN * CC) return;
    int n = idx >> 4, c = idx & 15;

    float m = b2[c];
    const float4* hr = (const float4*)(g_hidden + (size_t)n * HH);
    #pragma unroll
    for (int k = 0; k < 16; k++) {
        float4 hv = hr[k];
        m = fmaf(hv.x, sw2[(4 * k + 0) * CC + c], m);
        m = fmaf(hv.y, sw2[(4 * k + 1) * CC + c], m);
        m = fmaf(hv.z, sw2[(4 * k + 2) * CC + c], m);
        m = fmaf(hv.w, sw2[(4 * k + 3) * CC + c], m);
    }

    float a0 = att[n * 2 + 0], a1 = att[n * 2 + 1];
    float mx = fmaxf(a0, a1);
    float e0 = expf(a0 - mx), e1 = expf(a1 - mx);
    float inv = 1.f / (e0 + e1);

    float sa = 1.f / (1.f + expf(-alpha[n]));
    float logits = g_hg[idx] * (e0 * inv) + g_hg[(size_t)(NN + n) * CC + c] * (e1 * inv);
    out[idx] = sa * logits + (1.f - sa) * m;
}

// ---------------- launcher ----------------
extern "C" void kernel_launch(void* const* d_in, const int* in_sizes, int n_in,
                              void* d_out, int out_size) {
    (void)in_sizes; (void)n_in; (void)out_size;
    const float* features   = (const float*)d_in[0];
    const float* label_init = (const float*)d_in[1];
    const float* one_hot    = (const float*)d_in[2];
    const float* alpha      = (const float*)d_in[3];
    const float* attention  = (const float*)d_in[4];
    const float* e_edge     = (const float*)d_in[5];
    const float* w1         = (const float*)d_in[6];
    const float* b1         = (const float*)d_in[7];
    const float* w2         = (const float*)d_in[8];
    const float* b2         = (const float*)d_in[9];
    const int*   src        = (const int*)d_in[10];
    const int*   dst        = (const int*)d_in[11];
    const int*   train      = (const int*)d_in[12];
    float*       out        = (float*)d_out;

    prep_kernel<<<(NN * CC / 2 + 255) / 256, 256>>>(train, w1, label_init, one_hot); // 1
    hist_kernel<<<EB4, 256>>>(dst);                                                  // 2
    scan_fused_kernel<<<NBLK2, 1024>>>();                                            // 3
    scatter_gemm_kernel<<<GEMM_BLKS + EB4, 256>>>(src, dst, e_edge, features, b1);   // 4 (ncu)
    prop_kernel<0><<<PB2, 256>>>(one_hot);                                           // 5
    prop_kernel<1><<<PB2, 256>>>(one_hot);                                           // 6
    final_kernel<<<FB, 256>>>(w2, b2, attention, alpha, out);                        // 7
}